// round 7
// baseline (speedup 1.0000x reference)
#include <cuda_runtime.h>

#define BATCH 512
#define CIN   12
#define LIN   5000
#define C1    32
#define K1    50
#define S1    10
#define L1    496
#define C2    32
#define K2    25
#define S2    5
#define L2    95
#define LAT   32
#define HID   64
#define TSTEPS L2
#define EPS   1e-5f

// conv1 weights as tap-pairs: [ci][jp(25)][oc(32)] float2 {w[2jp], w[2jp+1]}
// conv2 weights padded per-oc: [oc][ci][28]
#define C2_WPAD 28
#define C2_OCSTR (C2 * C2_WPAD)          // 896 floats per oc

// ---------------- device scratch (no allocation allowed) ----------------
__device__ __align__(16) float2 g_w1[CIN * 25 * C1];
__device__ __align__(16) float g_w2p[C2 * C2_OCSTR];
__device__ float g_y1[BATCH * C1 * L1];
__device__ float g_y2[BATCH * C2 * L2];
__device__ float g_xt[TSTEPS * BATCH * LAT];
__device__ float g_stats1[64];
__device__ float g_stats2[64];
__device__ float g_bn1[64];
__device__ float g_bn2[64];

__device__ __forceinline__ float warp_sum(float v) {
    #pragma unroll
    for (int o = 16; o; o >>= 1) v += __shfl_xor_sync(0xffffffffu, v, o);
    return v;
}

// ---------------- kernel 0: zero stats + build weight layouts ----------
__global__ __launch_bounds__(256) void prep_kernel(
    const float* __restrict__ c1w, const float* __restrict__ c2w)
{
    int gid = blockIdx.x * 256 + threadIdx.x;
    int stride = gridDim.x * 256;
    if (gid < 64) { g_stats1[gid] = 0.f; g_stats2[gid] = 0.f; }
    // conv1: idx = (ci*25 + jp)*32 + oc
    for (int i = gid; i < CIN * 25 * C1; i += stride) {
        int oc = i & 31;
        int rest = i >> 5;
        int jp = rest % 25;
        int ci = rest / 25;
        const float* ws = c1w + (oc * CIN + ci) * K1 + 2 * jp;
        g_w1[i] = make_float2(ws[0], ws[1]);
    }
    // conv2: [oc][ci][28] padded
    for (int i = gid; i < C2 * C2_OCSTR; i += stride) {
        int j = i % C2_WPAD;
        int rest = i / C2_WPAD;          // oc*32 + ci
        g_w2p[i] = (j < K2) ? c2w[rest * K2 + j] : 0.f;
    }
}

// ---------------- kernel 1: conv1 + BN1 partial stats ----------------
// grid (4, 512): 128-position tiles. block 128 = 4 warps; warp -> 8 oc,
// ALL 128 tile positions: thread = 8 oc x 4 positions (lane + 32g).
// Per tap-pair: 4 LDS.64 (conflict-free) + 4 uniform LDG.128 + 64 FFMA.
#define C1_TILE 128
#define C1_XROW 1320                     // 127*10 + 50
#define SMEM1_BYTES (CIN * C1_XROW * 4)  // 63360

__global__ __launch_bounds__(128) void conv1_kernel(
    const float* __restrict__ x, const float* __restrict__ bias)
{
    extern __shared__ float x_s[];       // [12][1320]

    const int b     = blockIdx.y;
    const int tbase = blockIdx.x * C1_TILE;
    const int tid   = threadIdx.x;

    // fill tile (float4, zero past end of row)
    const int xstart = tbase * S1;       // multiple of 1280 -> 16B aligned
    const int avail  = LIN - xstart;
    for (int i = tid; i < CIN * (C1_XROW / 4); i += 128) {
        int ci = i / (C1_XROW / 4), j4 = i % (C1_XROW / 4);
        const float* src = x + ((size_t)b * CIN + ci) * LIN + xstart;
        float4 v;
        int j = j4 * 4;
        if (j + 3 < avail) {
            v = __ldg(reinterpret_cast<const float4*>(src) + j4);
        } else {
            v.x = (j + 0 < avail) ? __ldg(src + j + 0) : 0.f;
            v.y = (j + 1 < avail) ? __ldg(src + j + 1) : 0.f;
            v.z = (j + 2 < avail) ? __ldg(src + j + 2) : 0.f;
            v.w = (j + 3 < avail) ? __ldg(src + j + 3) : 0.f;
        }
        reinterpret_cast<float4*>(x_s + ci * C1_XROW)[j4] = v;
    }
    __syncthreads();

    const int lane = tid & 31;
    const int oc0  = (tid >> 5) * 8;
    const int p0 = lane * S1;            // even -> 8B aligned
    const int p1 = p0 + 320;
    const int p2 = p0 + 640;
    const int p3 = p0 + 960;             // max 310+960+48+1 = 1319 OK

    float acc[8][4];
    #pragma unroll
    for (int u = 0; u < 8; u++) {
        acc[u][0] = 0.f; acc[u][1] = 0.f; acc[u][2] = 0.f; acc[u][3] = 0.f;
    }

    for (int ci = 0; ci < CIN; ci++) {
        const float* xr = x_s + ci * C1_XROW;
        const float2* wr = g_w1 + ci * (25 * C1) + oc0;
        #pragma unroll 5
        for (int jp = 0; jp < 25; jp++) {
            float2 x0 = *reinterpret_cast<const float2*>(xr + p0 + 2 * jp);
            float2 x1 = *reinterpret_cast<const float2*>(xr + p1 + 2 * jp);
            float2 x2 = *reinterpret_cast<const float2*>(xr + p2 + 2 * jp);
            float2 x3 = *reinterpret_cast<const float2*>(xr + p3 + 2 * jp);
            const float4* w4 = reinterpret_cast<const float4*>(wr + jp * C1);
            float4 wa = __ldg(w4 + 0);   // oc0, oc0+1
            float4 wb = __ldg(w4 + 1);
            float4 wc = __ldg(w4 + 2);
            float4 wd = __ldg(w4 + 3);
            acc[0][0] += wa.x * x0.x + wa.y * x0.y;
            acc[0][1] += wa.x * x1.x + wa.y * x1.y;
            acc[0][2] += wa.x * x2.x + wa.y * x2.y;
            acc[0][3] += wa.x * x3.x + wa.y * x3.y;
            acc[1][0] += wa.z * x0.x + wa.w * x0.y;
            acc[1][1] += wa.z * x1.x + wa.w * x1.y;
            acc[1][2] += wa.z * x2.x + wa.w * x2.y;
            acc[1][3] += wa.z * x3.x + wa.w * x3.y;
            acc[2][0] += wb.x * x0.x + wb.y * x0.y;
            acc[2][1] += wb.x * x1.x + wb.y * x1.y;
            acc[2][2] += wb.x * x2.x + wb.y * x2.y;
            acc[2][3] += wb.x * x3.x + wb.y * x3.y;
            acc[3][0] += wb.z * x0.x + wb.w * x0.y;
            acc[3][1] += wb.z * x1.x + wb.w * x1.y;
            acc[3][2] += wb.z * x2.x + wb.w * x2.y;
            acc[3][3] += wb.z * x3.x + wb.w * x3.y;
            acc[4][0] += wc.x * x0.x + wc.y * x0.y;
            acc[4][1] += wc.x * x1.x + wc.y * x1.y;
            acc[4][2] += wc.x * x2.x + wc.y * x2.y;
            acc[4][3] += wc.x * x3.x + wc.y * x3.y;
            acc[5][0] += wc.z * x0.x + wc.w * x0.y;
            acc[5][1] += wc.z * x1.x + wc.w * x1.y;
            acc[5][2] += wc.z * x2.x + wc.w * x2.y;
            acc[5][3] += wc.z * x3.x + wc.w * x3.y;
            acc[6][0] += wd.x * x0.x + wd.y * x0.y;
            acc[6][1] += wd.x * x1.x + wd.y * x1.y;
            acc[6][2] += wd.x * x2.x + wd.y * x2.y;
            acc[6][3] += wd.x * x3.x + wd.y * x3.y;
            acc[7][0] += wd.z * x0.x + wd.w * x0.y;
            acc[7][1] += wd.z * x1.x + wd.w * x1.y;
            acc[7][2] += wd.z * x2.x + wd.w * x2.y;
            acc[7][3] += wd.z * x3.x + wd.w * x3.y;
        }
    }

    const bool ok[4] = { tbase + lane < L1, tbase + lane + 32 < L1,
                         tbase + lane + 64 < L1, tbase + lane + 96 < L1 };
    #pragma unroll
    for (int u = 0; u < 8; u++) {
        int oc = oc0 + u;
        float bsv = __ldg(bias + oc);
        float* yo = g_y1 + ((size_t)b * C1 + oc) * L1 + tbase + lane;
        float s = 0.f, s2 = 0.f;
        #pragma unroll
        for (int g = 0; g < 4; g++) {
            float v = acc[u][g] + bsv;
            if (ok[g]) {
                yo[32 * g] = v;
                s += v;
                s2 += v * v;
            }
        }
        s  = warp_sum(s);
        s2 = warp_sum(s2);
        if (lane == 0) {
            atomicAdd(&g_stats1[oc], s);
            atomicAdd(&g_stats1[32 + oc], s2);
        }
    }
}

// ---------------- kernel 2: BN finalize ----------------
__global__ void bn_finalize_kernel(int which, const float* __restrict__ g,
                                   const float* __restrict__ bsh, float invN)
{
    int c = threadIdx.x;
    if (c < 32) {
        const float* st = which ? g_stats2 : g_stats1;
        float* out = which ? g_bn2 : g_bn1;
        float m = st[c] * invN;
        float v = st[32 + c] * invN - m * m;
        float sc = g[c] * rsqrtf(v + EPS);
        out[c] = sc;
        out[32 + c] = bsh[c] - m * sc;
    }
}

// ---------------- kernel 3: conv2 (BN1+relu at load) + BN2 stats ------
// Measured-best config: grid 512; block 256 = 8 warps; warp -> 4 oc;
// lane -> t2 = {lane, lane+32, lane+64}; 12 accumulators/thread.
#define SMEM2_FLOATS (C2 * L1)            // 15872
#define SMEM2_BYTES  (SMEM2_FLOATS * 4)   // 63488

__global__ __launch_bounds__(256) void conv2_kernel(const float* __restrict__ bias)
{
    extern __shared__ float a_s[];        // [32][496]

    const int b = blockIdx.x;
    const int tid = threadIdx.x;

    const float4* y1v = reinterpret_cast<const float4*>(g_y1 + (size_t)b * C2 * L1);
    float4* av = reinterpret_cast<float4*>(a_s);
    for (int i = tid; i < C2 * 124; i += 256) {
        int ci = i / 124;
        float sc = g_bn1[ci], sh = g_bn1[32 + ci];
        float4 v = __ldg(y1v + i);
        v.x = fmaxf(v.x * sc + sh, 0.f);
        v.y = fmaxf(v.y * sc + sh, 0.f);
        v.z = fmaxf(v.z * sc + sh, 0.f);
        v.w = fmaxf(v.w * sc + sh, 0.f);
        av[i] = v;
    }
    __syncthreads();

    const int lane = tid & 31;
    const int oc0  = (tid >> 5) * 4;
    const int p0 = lane * S2;
    const int p1 = p0 + 160;
    const bool ok2 = (lane + 64 < L2);
    const int p2 = ok2 ? p0 + 320 : 0;

    float acc[4][3];
    #pragma unroll
    for (int u = 0; u < 4; u++) { acc[u][0] = 0.f; acc[u][1] = 0.f; acc[u][2] = 0.f; }

    for (int ci = 0; ci < C2; ci++) {
        const float* xr = a_s + ci * L1;
        const float* wr = g_w2p + oc0 * C2_OCSTR + ci * C2_WPAD;
        #pragma unroll
        for (int j = 0; j < 24; j += 4) {
            float x00 = xr[p0 + j], x01 = xr[p0 + j + 1], x02 = xr[p0 + j + 2], x03 = xr[p0 + j + 3];
            float x10 = xr[p1 + j], x11 = xr[p1 + j + 1], x12 = xr[p1 + j + 2], x13 = xr[p1 + j + 3];
            float x20 = xr[p2 + j], x21 = xr[p2 + j + 1], x22 = xr[p2 + j + 2], x23 = xr[p2 + j + 3];
            #pragma unroll
            for (int u = 0; u < 4; u++) {
                float4 wv = __ldg(reinterpret_cast<const float4*>(wr + u * C2_OCSTR + j));
                acc[u][0] += wv.x * x00 + wv.y * x01 + wv.z * x02 + wv.w * x03;
                acc[u][1] += wv.x * x10 + wv.y * x11 + wv.z * x12 + wv.w * x13;
                acc[u][2] += wv.x * x20 + wv.y * x21 + wv.z * x22 + wv.w * x23;
            }
        }
        { // tap 24
            float x0 = xr[p0 + 24], x1 = xr[p1 + 24], x2 = xr[p2 + 24];
            #pragma unroll
            for (int u = 0; u < 4; u++) {
                float wv = __ldg(wr + u * C2_OCSTR + 24);
                acc[u][0] += wv * x0;
                acc[u][1] += wv * x1;
                acc[u][2] += wv * x2;
            }
        }
    }

    #pragma unroll
    for (int u = 0; u < 4; u++) {
        int oc = oc0 + u;
        float bsv = __ldg(bias + oc);
        float v0 = acc[u][0] + bsv;
        float v1 = acc[u][1] + bsv;
        float v2 = acc[u][2] + bsv;
        float* yo = g_y2 + ((size_t)b * C2 + oc) * L2;
        yo[lane] = v0;
        yo[lane + 32] = v1;
        if (ok2) yo[lane + 64] = v2;
        float s  = v0 + v1 + (ok2 ? v2 : 0.f);
        float s2 = v0 * v0 + v1 * v1 + (ok2 ? v2 * v2 : 0.f);
        s  = warp_sum(s);
        s2 = warp_sum(s2);
        if (lane == 0) {
            atomicAdd(&g_stats2[oc], s);
            atomicAdd(&g_stats2[32 + oc], s2);
        }
    }
}

// ---------------- kernel 4: BN2+relu, input projection, LN1 ----------
__global__ __launch_bounds__(256) void proj_kernel(
    const float* __restrict__ Wi, const float* __restrict__ bi,
    const float* __restrict__ ln1g, const float* __restrict__ ln1b)
{
    __shared__ float a_s[C2 * L2];
    __shared__ float Wi_s[32 * 33];

    const int b = blockIdx.x;
    const int tid = threadIdx.x;
    for (int i = tid; i < C2 * L2; i += 256) {
        int c = i / L2;
        float v = g_y2[(size_t)b * C2 * L2 + i];
        a_s[i] = fmaxf(v * g_bn2[c] + g_bn2[32 + c], 0.f);
    }
    for (int i = tid; i < 32 * 32; i += 256)
        Wi_s[(i >> 5) * 33 + (i & 31)] = Wi[i];
    __syncthreads();

    const int lane = tid & 31;
    const int wp = tid >> 5;
    const float biv = bi[lane];
    const float gv = ln1g[lane], bv = ln1b[lane];

    for (int t = wp; t < L2; t += 8) {
        float z = biv;
        #pragma unroll
        for (int c = 0; c < 32; c++)
            z += Wi_s[lane * 33 + c] * a_s[c * L2 + t];
        float m = warp_sum(z) * (1.f / 32.f);
        float d = z - m;
        float var = warp_sum(d * d) * (1.f / 32.f);
        float r = rsqrtf(var + EPS);
        g_xt[((size_t)t * BATCH + b) * LAT + lane] = d * r * gv + bv;
    }
}

// ---------------- kernel 5: recurrent scan + pool + output proj -------
__global__ __launch_bounds__(128) void rnn_kernel(
    const float* __restrict__ Wh, const float* __restrict__ bh,
    const float* __restrict__ ln2g, const float* __restrict__ ln2b,
    const float* __restrict__ Wr, const float* __restrict__ br,
    const float* __restrict__ Wo, const float* __restrict__ bo,
    float* __restrict__ out)
{
    __shared__ float Wh_s[64 * 33];
    __shared__ float Wr_s[32 * 65];
    __shared__ float Wo_s[32 * 33];

    const int tid = threadIdx.x;
    const int lane = tid & 31;
    const int wp = tid >> 5;
    for (int i = tid; i < 64 * 32; i += 128) Wh_s[(i >> 5) * 33 + (i & 31)] = Wh[i];
    for (int i = tid; i < 32 * 64; i += 128) Wr_s[(i / 64) * 65 + (i % 64)] = Wr[i];
    for (int i = tid; i < 32 * 32; i += 128) Wo_s[(i >> 5) * 33 + (i & 31)] = Wo[i];
    __syncthreads();

    const int b = blockIdx.x * 4 + wp;
    const float bh0 = bh[lane], bh1 = bh[lane + 32];
    const float gA = ln2g[lane], bA = ln2b[lane];
    const float gB = ln2g[lane + 32], bB = ln2b[lane + 32];
    const float brl = br[lane];

    float h = 0.f, psum = 0.f;
    for (int t = 0; t < TSTEPS; t++) {
        float c = g_xt[((size_t)t * BATCH + b) * LAT + lane] + h;
        float a0a = bh0, a0b = 0.f, a1a = bh1, a1b = 0.f;
        #pragma unroll
        for (int j = 0; j < 32; j += 2) {
            float cj0 = __shfl_sync(0xffffffffu, c, j);
            float cj1 = __shfl_sync(0xffffffffu, c, j + 1);
            a0a += Wh_s[lane * 33 + j] * cj0;
            a0b += Wh_s[lane * 33 + j + 1] * cj1;
            a1a += Wh_s[(lane + 32) * 33 + j] * cj0;
            a1b += Wh_s[(lane + 32) * 33 + j + 1] * cj1;
        }
        float a0 = fmaxf(a0a + a0b, 0.f);
        float a1 = fmaxf(a1a + a1b, 0.f);
        float m = warp_sum(a0 + a1) * (1.f / 64.f);
        float d0 = a0 - m, d1 = a1 - m;
        float var = warp_sum(d0 * d0 + d1 * d1) * (1.f / 64.f);
        float r = rsqrtf(var + EPS);
        float n0 = d0 * r * gA + bA;
        float n1 = d1 * r * gB + bB;
        float acca = brl, accb = 0.f;
        #pragma unroll
        for (int i = 0; i < 32; i++) {
            float v0 = __shfl_sync(0xffffffffu, n0, i);
            float v1 = __shfl_sync(0xffffffffu, n1, i);
            acca += Wr_s[lane * 65 + i] * v0;
            accb += Wr_s[lane * 65 + 32 + i] * v1;
        }
        h = tanhf(acca + accb);
        psum += h;
    }
    float p = psum * (1.f / (float)TSTEPS);
    float o = bo[lane];
    #pragma unroll
    for (int j = 0; j < 32; j++)
        o += Wo_s[lane * 33 + j] * __shfl_sync(0xffffffffu, p, j);
    out[b * 32 + lane] = o;
}

// ---------------- launch ----------------
extern "C" void kernel_launch(void* const* d_in, const int* in_sizes, int n_in,
                              void* d_out, int out_size)
{
    const float* x    = (const float*)d_in[0];
    const float* c1w  = (const float*)d_in[1];
    const float* c1b  = (const float*)d_in[2];
    const float* bn1g = (const float*)d_in[3];
    const float* bn1b = (const float*)d_in[4];
    const float* c2w  = (const float*)d_in[5];
    const float* c2b  = (const float*)d_in[6];
    const float* bn2g = (const float*)d_in[7];
    const float* bn2b = (const float*)d_in[8];
    const float* Wi   = (const float*)d_in[9];
    const float* bi   = (const float*)d_in[10];
    const float* ln1g = (const float*)d_in[11];
    const float* ln1b = (const float*)d_in[12];
    const float* Wh   = (const float*)d_in[13];
    const float* bh   = (const float*)d_in[14];
    const float* ln2g = (const float*)d_in[15];
    const float* ln2b = (const float*)d_in[16];
    const float* Wr   = (const float*)d_in[17];
    const float* br   = (const float*)d_in[18];
    const float* Wo   = (const float*)d_in[19];
    const float* bo   = (const float*)d_in[20];
    float* out = (float*)d_out;

    static bool attr_done = false;
    if (!attr_done) {
        cudaFuncSetAttribute(conv1_kernel, cudaFuncAttributeMaxDynamicSharedMemorySize, SMEM1_BYTES);
        cudaFuncSetAttribute(conv2_kernel, cudaFuncAttributeMaxDynamicSharedMemorySize, SMEM2_BYTES);
        attr_done = true;
    }

    prep_kernel<<<64, 256>>>(c1w, c2w);
    conv1_kernel<<<dim3(4, BATCH), 128, SMEM1_BYTES>>>(x, c1b);
    bn_finalize_kernel<<<1, 32>>>(0, bn1g, bn1b, 1.f / (float)(BATCH * L1));
    conv2_kernel<<<BATCH, 256, SMEM2_BYTES>>>(c2b);
    bn_finalize_kernel<<<1, 32>>>(1, bn2g, bn2b, 1.f / (float)(BATCH * L2));
    proj_kernel<<<BATCH, 256>>>(Wi, bi, ln1g, ln1b);
    rnn_kernel<<<BATCH / 4, 128>>>(Wh, bh, ln2g, ln2b, Wr, br, Wo, bo, out);
}

// round 8
// speedup vs baseline: 1.4750x; 1.4750x over previous
#include <cuda_runtime.h>

#define BATCH 512
#define CIN   12
#define LIN   5000
#define C1    32
#define K1    50
#define S1    10
#define L1    496
#define C2    32
#define K2    25
#define S2    5
#define L2    95
#define LAT   32
#define HID   64
#define TSTEPS L2
#define EPS   1e-5f

// conv1 weights as tap-pairs: [ci][jp(25)][oc(32)] float2 {w[2jp], w[2jp+1]}
// conv2 weights padded per-oc: [oc][ci][28]
#define C2_WPAD 28
#define C2_OCSTR (C2 * C2_WPAD)          // 896 floats per oc

// ---------------- device scratch (no allocation allowed) ----------------
__device__ __align__(16) float2 g_w1[CIN * 25 * C1];
__device__ __align__(16) float g_w2p[C2 * C2_OCSTR];
__device__ float g_y1[BATCH * C1 * L1];
__device__ float g_y2[BATCH * C2 * L2];
__device__ float g_xt[TSTEPS * BATCH * LAT];
__device__ float g_stats1[64];
__device__ float g_stats2[64];

__device__ __forceinline__ float warp_sum(float v) {
    #pragma unroll
    for (int o = 16; o; o >>= 1) v += __shfl_xor_sync(0xffffffffu, v, o);
    return v;
}

// ---------------- kernel 0: zero stats + build weight layouts ----------
__global__ __launch_bounds__(256) void prep_kernel(
    const float* __restrict__ c1w, const float* __restrict__ c2w)
{
    int gid = blockIdx.x * 256 + threadIdx.x;
    int stride = gridDim.x * 256;
    if (gid < 64) { g_stats1[gid] = 0.f; g_stats2[gid] = 0.f; }
    // conv1: idx = (ci*25 + jp)*32 + oc
    for (int i = gid; i < CIN * 25 * C1; i += stride) {
        int oc = i & 31;
        int rest = i >> 5;
        int jp = rest % 25;
        int ci = rest / 25;
        const float* ws = c1w + (oc * CIN + ci) * K1 + 2 * jp;
        g_w1[i] = make_float2(ws[0], ws[1]);
    }
    // conv2: [oc][ci][28] padded
    for (int i = gid; i < C2 * C2_OCSTR; i += stride) {
        int j = i % C2_WPAD;
        int rest = i / C2_WPAD;          // oc*32 + ci
        g_w2p[i] = (j < K2) ? c2w[rest * K2 + j] : 0.f;
    }
}

// ---------------- kernel 1: conv1 + BN1 partial stats ----------------
// grid (8, 512); block 128 = 4 warps; warp -> 8 oc; lane -> t0 = tbase+lane,
// t1 = t0+32. x via conflict-free LDS.64. Weights staged per-ci into a
// double-buffered smem ring (6.4 KB slice), prefetched into registers
// during the previous ci's compute -> no L1/L2 latency on the weight path.
#define C1_XROW 680
#define W1_SLICE4 400     // float4 per ci slice (25*32 float2)

__global__ __launch_bounds__(128) void conv1_kernel(
    const float* __restrict__ x, const float* __restrict__ bias)
{
    __shared__ float x_s[CIN * C1_XROW];               // 32640 B
    __shared__ __align__(16) float2 w_s[2][25 * C1];   // 2 x 6400 B

    const int b     = blockIdx.y;
    const int tbase = blockIdx.x * 64;
    const int tid   = threadIdx.x;

    const int xstart = tbase * S1;
    const int avail  = LIN - xstart;
    for (int i = tid; i < CIN * C1_XROW; i += 128) {
        int ci = i / C1_XROW, p = i % C1_XROW;
        x_s[i] = (p < avail) ? __ldg(x + (size_t)(b * CIN + ci) * LIN + xstart + p) : 0.f;
    }
    // stage ci=0 weight slice
    const float4* wsrc = reinterpret_cast<const float4*>(g_w1);
    for (int i = tid; i < W1_SLICE4; i += 128)
        reinterpret_cast<float4*>(w_s[0])[i] = __ldg(wsrc + i);
    __syncthreads();

    const int lane = tid & 31;
    const int oc0  = (tid >> 5) * 8;
    const int p0   = lane * S1;          // even -> 8B aligned
    const int p1   = p0 + 320;

    float acc[8][2];
    #pragma unroll
    for (int u = 0; u < 8; u++) { acc[u][0] = 0.f; acc[u][1] = 0.f; }

    for (int ci = 0; ci < CIN; ci++) {
        const int cur = ci & 1;
        const bool hasNext = (ci + 1 < CIN);
        // prefetch next slice into registers (latency overlapped with compute)
        float4 pf0, pf1, pf2, pf3;
        if (hasNext) {
            const float4* nsrc = wsrc + (ci + 1) * W1_SLICE4;
            if (tid       < W1_SLICE4) pf0 = __ldg(nsrc + tid);
            if (tid + 128 < W1_SLICE4) pf1 = __ldg(nsrc + tid + 128);
            if (tid + 256 < W1_SLICE4) pf2 = __ldg(nsrc + tid + 256);
            if (tid + 384 < W1_SLICE4) pf3 = __ldg(nsrc + tid + 384);
        }

        const float* xr = x_s + ci * C1_XROW;
        const float2* wr = w_s[cur] + oc0;
        #pragma unroll 5
        for (int jp = 0; jp < 25; jp++) {
            float2 xv0 = *reinterpret_cast<const float2*>(xr + p0 + 2 * jp);
            float2 xv1 = *reinterpret_cast<const float2*>(xr + p1 + 2 * jp);
            const float4* w4 = reinterpret_cast<const float4*>(wr + jp * C1);
            float4 wa = w4[0];           // LDS.128 broadcast: oc0, oc0+1
            float4 wb = w4[1];
            float4 wc = w4[2];
            float4 wd = w4[3];
            acc[0][0] += wa.x * xv0.x + wa.y * xv0.y;
            acc[0][1] += wa.x * xv1.x + wa.y * xv1.y;
            acc[1][0] += wa.z * xv0.x + wa.w * xv0.y;
            acc[1][1] += wa.z * xv1.x + wa.w * xv1.y;
            acc[2][0] += wb.x * xv0.x + wb.y * xv0.y;
            acc[2][1] += wb.x * xv1.x + wb.y * xv1.y;
            acc[3][0] += wb.z * xv0.x + wb.w * xv0.y;
            acc[3][1] += wb.z * xv1.x + wb.w * xv1.y;
            acc[4][0] += wc.x * xv0.x + wc.y * xv0.y;
            acc[4][1] += wc.x * xv1.x + wc.y * xv1.y;
            acc[5][0] += wc.z * xv0.x + wc.w * xv0.y;
            acc[5][1] += wc.z * xv1.x + wc.w * xv1.y;
            acc[6][0] += wd.x * xv0.x + wd.y * xv0.y;
            acc[6][1] += wd.x * xv1.x + wd.y * xv1.y;
            acc[7][0] += wd.z * xv0.x + wd.w * xv0.y;
            acc[7][1] += wd.z * xv1.x + wd.w * xv1.y;
        }

        if (hasNext) {
            __syncthreads();   // all warps done reading buffer cur^1
            float4* dst = reinterpret_cast<float4*>(w_s[cur ^ 1]);
            if (tid       < W1_SLICE4) dst[tid]       = pf0;
            if (tid + 128 < W1_SLICE4) dst[tid + 128] = pf1;
            if (tid + 256 < W1_SLICE4) dst[tid + 256] = pf2;
            if (tid + 384 < W1_SLICE4) dst[tid + 384] = pf3;
            __syncthreads();
        }
    }

    const int t0g = tbase + lane;
    const int t1g = t0g + 32;
    const bool ok1 = (t1g < L1);
    #pragma unroll
    for (int u = 0; u < 8; u++) {
        int oc = oc0 + u;
        float bsv = __ldg(bias + oc);
        float v0 = acc[u][0] + bsv;
        float v1 = acc[u][1] + bsv;
        g_y1[((size_t)b * C1 + oc) * L1 + t0g] = v0;
        if (ok1) g_y1[((size_t)b * C1 + oc) * L1 + t1g] = v1;
        float s  = v0 + (ok1 ? v1 : 0.f);
        float s2 = v0 * v0 + (ok1 ? v1 * v1 : 0.f);
        s  = warp_sum(s);
        s2 = warp_sum(s2);
        if (lane == 0) {
            atomicAdd(&g_stats1[oc], s);
            atomicAdd(&g_stats1[32 + oc], s2);
        }
    }
}

// ---------------- kernel 3: conv2 (BN1 finalize+relu fused) + BN2 stats
// Measured-best config: grid 512; block 256 = 8 warps; warp -> 4 oc;
// lane -> t2 = {lane, lane+32, lane+64}; 12 accumulators/thread.
#define SMEM2_FLOATS (C2 * L1)            // 15872
#define SMEM2_BYTES  (SMEM2_FLOATS * 4)   // 63488

__global__ __launch_bounds__(256) void conv2_kernel(
    const float* __restrict__ bias,
    const float* __restrict__ bn1g, const float* __restrict__ bn1b)
{
    extern __shared__ float a_s[];        // [32][496]
    __shared__ float bn1_s[64];           // scale[32], shift[32]

    const int b = blockIdx.x;
    const int tid = threadIdx.x;

    if (tid < 32) {
        const float invN = 1.f / (float)(BATCH * L1);
        float m = g_stats1[tid] * invN;
        float v = g_stats1[32 + tid] * invN - m * m;
        float sc = bn1g[tid] * rsqrtf(v + EPS);
        bn1_s[tid] = sc;
        bn1_s[32 + tid] = bn1b[tid] - m * sc;
    }
    __syncthreads();

    const float4* y1v = reinterpret_cast<const float4*>(g_y1 + (size_t)b * C2 * L1);
    float4* av = reinterpret_cast<float4*>(a_s);
    for (int i = tid; i < C2 * 124; i += 256) {
        int ci = i / 124;
        float sc = bn1_s[ci], sh = bn1_s[32 + ci];
        float4 v = __ldg(y1v + i);
        v.x = fmaxf(v.x * sc + sh, 0.f);
        v.y = fmaxf(v.y * sc + sh, 0.f);
        v.z = fmaxf(v.z * sc + sh, 0.f);
        v.w = fmaxf(v.w * sc + sh, 0.f);
        av[i] = v;
    }
    __syncthreads();

    const int lane = tid & 31;
    const int oc0  = (tid >> 5) * 4;
    const int p0 = lane * S2;
    const int p1 = p0 + 160;
    const bool ok2 = (lane + 64 < L2);
    const int p2 = ok2 ? p0 + 320 : 0;

    float acc[4][3];
    #pragma unroll
    for (int u = 0; u < 4; u++) { acc[u][0] = 0.f; acc[u][1] = 0.f; acc[u][2] = 0.f; }

    for (int ci = 0; ci < C2; ci++) {
        const float* xr = a_s + ci * L1;
        const float* wr = g_w2p + oc0 * C2_OCSTR + ci * C2_WPAD;
        #pragma unroll
        for (int j = 0; j < 24; j += 4) {
            float x00 = xr[p0 + j], x01 = xr[p0 + j + 1], x02 = xr[p0 + j + 2], x03 = xr[p0 + j + 3];
            float x10 = xr[p1 + j], x11 = xr[p1 + j + 1], x12 = xr[p1 + j + 2], x13 = xr[p1 + j + 3];
            float x20 = xr[p2 + j], x21 = xr[p2 + j + 1], x22 = xr[p2 + j + 2], x23 = xr[p2 + j + 3];
            #pragma unroll
            for (int u = 0; u < 4; u++) {
                float4 wv = __ldg(reinterpret_cast<const float4*>(wr + u * C2_OCSTR + j));
                acc[u][0] += wv.x * x00 + wv.y * x01 + wv.z * x02 + wv.w * x03;
                acc[u][1] += wv.x * x10 + wv.y * x11 + wv.z * x12 + wv.w * x13;
                acc[u][2] += wv.x * x20 + wv.y * x21 + wv.z * x22 + wv.w * x23;
            }
        }
        { // tap 24
            float x0 = xr[p0 + 24], x1 = xr[p1 + 24], x2 = xr[p2 + 24];
            #pragma unroll
            for (int u = 0; u < 4; u++) {
                float wv = __ldg(wr + u * C2_OCSTR + 24);
                acc[u][0] += wv * x0;
                acc[u][1] += wv * x1;
                acc[u][2] += wv * x2;
            }
        }
    }

    #pragma unroll
    for (int u = 0; u < 4; u++) {
        int oc = oc0 + u;
        float bsv = __ldg(bias + oc);
        float v0 = acc[u][0] + bsv;
        float v1 = acc[u][1] + bsv;
        float v2 = acc[u][2] + bsv;
        float* yo = g_y2 + ((size_t)b * C2 + oc) * L2;
        yo[lane] = v0;
        yo[lane + 32] = v1;
        if (ok2) yo[lane + 64] = v2;
        float s  = v0 + v1 + (ok2 ? v2 : 0.f);
        float s2 = v0 * v0 + v1 * v1 + (ok2 ? v2 * v2 : 0.f);
        s  = warp_sum(s);
        s2 = warp_sum(s2);
        if (lane == 0) {
            atomicAdd(&g_stats2[oc], s);
            atomicAdd(&g_stats2[32 + oc], s2);
        }
    }
}

// ---------------- kernel 4: BN2 finalize+relu, input projection, LN1 --
__global__ __launch_bounds__(256) void proj_kernel(
    const float* __restrict__ Wi, const float* __restrict__ bi,
    const float* __restrict__ ln1g, const float* __restrict__ ln1b,
    const float* __restrict__ bn2g, const float* __restrict__ bn2b)
{
    __shared__ float a_s[C2 * L2];
    __shared__ float Wi_s[32 * 33];
    __shared__ float bn2_s[64];

    const int b = blockIdx.x;
    const int tid = threadIdx.x;

    if (tid < 32) {
        const float invN = 1.f / (float)(BATCH * L2);
        float m = g_stats2[tid] * invN;
        float v = g_stats2[32 + tid] * invN - m * m;
        float sc = bn2g[tid] * rsqrtf(v + EPS);
        bn2_s[tid] = sc;
        bn2_s[32 + tid] = bn2b[tid] - m * sc;
    }
    __syncthreads();

    for (int i = tid; i < C2 * L2; i += 256) {
        int c = i / L2;
        float v = g_y2[(size_t)b * C2 * L2 + i];
        a_s[i] = fmaxf(v * bn2_s[c] + bn2_s[32 + c], 0.f);
    }
    for (int i = tid; i < 32 * 32; i += 256)
        Wi_s[(i >> 5) * 33 + (i & 31)] = Wi[i];
    __syncthreads();

    const int lane = tid & 31;
    const int wp = tid >> 5;
    const float biv = bi[lane];
    const float gv = ln1g[lane], bv = ln1b[lane];

    for (int t = wp; t < L2; t += 8) {
        float z = biv;
        #pragma unroll
        for (int c = 0; c < 32; c++)
            z += Wi_s[lane * 33 + c] * a_s[c * L2 + t];
        float m = warp_sum(z) * (1.f / 32.f);
        float d = z - m;
        float var = warp_sum(d * d) * (1.f / 32.f);
        float r = rsqrtf(var + EPS);
        g_xt[((size_t)t * BATCH + b) * LAT + lane] = d * r * gv + bv;
    }
}

// ---------------- kernel 5: recurrent scan + pool + output proj -------
__global__ __launch_bounds__(128) void rnn_kernel(
    const float* __restrict__ Wh, const float* __restrict__ bh,
    const float* __restrict__ ln2g, const float* __restrict__ ln2b,
    const float* __restrict__ Wr, const float* __restrict__ br,
    const float* __restrict__ Wo, const float* __restrict__ bo,
    float* __restrict__ out)
{
    __shared__ float Wh_s[64 * 33];
    __shared__ float Wr_s[32 * 65];
    __shared__ float Wo_s[32 * 33];

    const int tid = threadIdx.x;
    const int lane = tid & 31;
    const int wp = tid >> 5;
    for (int i = tid; i < 64 * 32; i += 128) Wh_s[(i >> 5) * 33 + (i & 31)] = Wh[i];
    for (int i = tid; i < 32 * 64; i += 128) Wr_s[(i / 64) * 65 + (i % 64)] = Wr[i];
    for (int i = tid; i < 32 * 32; i += 128) Wo_s[(i >> 5) * 33 + (i & 31)] = Wo[i];
    __syncthreads();

    const int b = blockIdx.x * 4 + wp;
    const float bh0 = bh[lane], bh1 = bh[lane + 32];
    const float gA = ln2g[lane], bA = ln2b[lane];
    const float gB = ln2g[lane + 32], bB = ln2b[lane + 32];
    const float brl = br[lane];

    float h = 0.f, psum = 0.f;
    for (int t = 0; t < TSTEPS; t++) {
        float c = g_xt[((size_t)t * BATCH + b) * LAT + lane] + h;
        float a0a = bh0, a0b = 0.f, a1a = bh1, a1b = 0.f;
        #pragma unroll
        for (int j = 0; j < 32; j += 2) {
            float cj0 = __shfl_sync(0xffffffffu, c, j);
            float cj1 = __shfl_sync(0xffffffffu, c, j + 1);
            a0a += Wh_s[lane * 33 + j] * cj0;
            a0b += Wh_s[lane * 33 + j + 1] * cj1;
            a1a += Wh_s[(lane + 32) * 33 + j] * cj0;
            a1b += Wh_s[(lane + 32) * 33 + j + 1] * cj1;
        }
        float a0 = fmaxf(a0a + a0b, 0.f);
        float a1 = fmaxf(a1a + a1b, 0.f);
        float m = warp_sum(a0 + a1) * (1.f / 64.f);
        float d0 = a0 - m, d1 = a1 - m;
        float var = warp_sum(d0 * d0 + d1 * d1) * (1.f / 64.f);
        float r = rsqrtf(var + EPS);
        float n0 = d0 * r * gA + bA;
        float n1 = d1 * r * gB + bB;
        float acca = brl, accb = 0.f;
        #pragma unroll
        for (int i = 0; i < 32; i++) {
            float v0 = __shfl_sync(0xffffffffu, n0, i);
            float v1 = __shfl_sync(0xffffffffu, n1, i);
            acca += Wr_s[lane * 65 + i] * v0;
            accb += Wr_s[lane * 65 + 32 + i] * v1;
        }
        h = tanhf(acca + accb);
        psum += h;
    }
    float p = psum * (1.f / (float)TSTEPS);
    float o = bo[lane];
    #pragma unroll
    for (int j = 0; j < 32; j++)
        o += Wo_s[lane * 33 + j] * __shfl_sync(0xffffffffu, p, j);
    out[b * 32 + lane] = o;
}

// ---------------- launch ----------------
extern "C" void kernel_launch(void* const* d_in, const int* in_sizes, int n_in,
                              void* d_out, int out_size)
{
    const float* x    = (const float*)d_in[0];
    const float* c1w  = (const float*)d_in[1];
    const float* c1b  = (const float*)d_in[2];
    const float* bn1g = (const float*)d_in[3];
    const float* bn1b = (const float*)d_in[4];
    const float* c2w  = (const float*)d_in[5];
    const float* c2b  = (const float*)d_in[6];
    const float* bn2g = (const float*)d_in[7];
    const float* bn2b = (const float*)d_in[8];
    const float* Wi   = (const float*)d_in[9];
    const float* bi   = (const float*)d_in[10];
    const float* ln1g = (const float*)d_in[11];
    const float* ln1b = (const float*)d_in[12];
    const float* Wh   = (const float*)d_in[13];
    const float* bh   = (const float*)d_in[14];
    const float* ln2g = (const float*)d_in[15];
    const float* ln2b = (const float*)d_in[16];
    const float* Wr   = (const float*)d_in[17];
    const float* br   = (const float*)d_in[18];
    const float* Wo   = (const float*)d_in[19];
    const float* bo   = (const float*)d_in[20];
    float* out = (float*)d_out;

    static bool attr_done = false;
    if (!attr_done) {
        cudaFuncSetAttribute(conv2_kernel, cudaFuncAttributeMaxDynamicSharedMemorySize, SMEM2_BYTES);
        attr_done = true;
    }

    prep_kernel<<<64, 256>>>(c1w, c2w);
    conv1_kernel<<<dim3(8, BATCH), 128>>>(x, c1b);
    conv2_kernel<<<BATCH, 256, SMEM2_BYTES>>>(c2b, bn1g, bn1b);
    proj_kernel<<<BATCH, 256>>>(Wi, bi, ln1g, ln1b, bn2g, bn2b);
    rnn_kernel<<<BATCH / 4, 128>>>(Wh, bh, ln2g, ln2b, Wr, br, Wo, bo, out);
}

// round 14
// speedup vs baseline: 1.4800x; 1.0034x over previous
#include <cuda_runtime.h>

#define BATCH 512
#define CIN   12
#define LIN   5000
#define C1    32
#define K1    50
#define S1    10
#define L1    496
#define C2    32
#define K2    25
#define S2    5
#define L2    95
#define LAT   32
#define HID   64
#define TSTEPS L2
#define EPS   1e-5f

// conv1 weights as tap-pairs: [ci][jp(25)][oc(32)] float2 {w[2jp], w[2jp+1]}
// conv2 weights: [ci][tap(25)][oc(32)] float
// ---------------- device scratch (no allocation allowed) ----------------
__device__ __align__(16) float2 g_w1[CIN * 25 * C1];
__device__ __align__(16) float g_w2s[C2 * 25 * C2];
__device__ float g_y1[BATCH * C1 * L1];
__device__ float g_y2[BATCH * C2 * L2];
__device__ float g_xt[TSTEPS * BATCH * LAT];
__device__ float g_stats1[64];
__device__ float g_stats2[64];

__device__ __forceinline__ float warp_sum(float v) {
    #pragma unroll
    for (int o = 16; o; o >>= 1) v += __shfl_xor_sync(0xffffffffu, v, o);
    return v;
}

// ---------------- kernel 0: zero stats + build weight layouts ----------
__global__ __launch_bounds__(256) void prep_kernel(
    const float* __restrict__ c1w, const float* __restrict__ c2w)
{
    int gid = blockIdx.x * 256 + threadIdx.x;
    int stride = gridDim.x * 256;
    if (gid < 64) { g_stats1[gid] = 0.f; g_stats2[gid] = 0.f; }
    // conv1: idx = (ci*25 + jp)*32 + oc
    for (int i = gid; i < CIN * 25 * C1; i += stride) {
        int oc = i & 31;
        int rest = i >> 5;
        int jp = rest % 25;
        int ci = rest / 25;
        const float* ws = c1w + (oc * CIN + ci) * K1 + 2 * jp;
        g_w1[i] = make_float2(ws[0], ws[1]);
    }
    // conv2: idx = (ci*25 + t)*32 + oc
    for (int i = gid; i < C2 * 25 * C2; i += stride) {
        int oc = i & 31;
        int rest = i >> 5;
        int t = rest % 25;
        int ci = rest / 25;
        g_w2s[i] = c2w[(oc * C2 + ci) * K2 + t];
    }
}

// ---------------- kernel 1: conv1 + BN1 partial stats ----------------
// grid (8, 512); block 128 = 4 warps; warp -> 8 oc; lane -> t0 = tbase+lane,
// t1 = t0+32. x via conflict-free LDS.64. Weights staged per-ci into a
// double-buffered smem ring, prefetched into registers during compute.
#define C1_XROW 680
#define W1_SLICE4 400     // float4 per ci slice (25*32 float2)

__global__ __launch_bounds__(128) void conv1_kernel(
    const float* __restrict__ x, const float* __restrict__ bias)
{
    __shared__ float x_s[CIN * C1_XROW];               // 32640 B
    __shared__ __align__(16) float2 w_s[2][25 * C1];   // 2 x 6400 B

    const int b     = blockIdx.y;
    const int tbase = blockIdx.x * 64;
    const int tid   = threadIdx.x;

    const int xstart = tbase * S1;
    const int avail  = LIN - xstart;
    for (int i = tid; i < CIN * C1_XROW; i += 128) {
        int ci = i / C1_XROW, p = i % C1_XROW;
        x_s[i] = (p < avail) ? __ldg(x + (size_t)(b * CIN + ci) * LIN + xstart + p) : 0.f;
    }
    const float4* wsrc = reinterpret_cast<const float4*>(g_w1);
    for (int i = tid; i < W1_SLICE4; i += 128)
        reinterpret_cast<float4*>(w_s[0])[i] = __ldg(wsrc + i);
    __syncthreads();

    const int lane = tid & 31;
    const int oc0  = (tid >> 5) * 8;
    const int p0   = lane * S1;
    const int p1   = p0 + 320;

    float acc[8][2];
    #pragma unroll
    for (int u = 0; u < 8; u++) { acc[u][0] = 0.f; acc[u][1] = 0.f; }

    for (int ci = 0; ci < CIN; ci++) {
        const int cur = ci & 1;
        const bool hasNext = (ci + 1 < CIN);
        float4 pf0, pf1, pf2, pf3;
        if (hasNext) {
            const float4* nsrc = wsrc + (ci + 1) * W1_SLICE4;
            if (tid       < W1_SLICE4) pf0 = __ldg(nsrc + tid);
            if (tid + 128 < W1_SLICE4) pf1 = __ldg(nsrc + tid + 128);
            if (tid + 256 < W1_SLICE4) pf2 = __ldg(nsrc + tid + 256);
            if (tid + 384 < W1_SLICE4) pf3 = __ldg(nsrc + tid + 384);
        }

        const float* xr = x_s + ci * C1_XROW;
        const float2* wr = w_s[cur] + oc0;
        #pragma unroll 5
        for (int jp = 0; jp < 25; jp++) {
            float2 xv0 = *reinterpret_cast<const float2*>(xr + p0 + 2 * jp);
            float2 xv1 = *reinterpret_cast<const float2*>(xr + p1 + 2 * jp);
            const float4* w4 = reinterpret_cast<const float4*>(wr + jp * C1);
            float4 wa = w4[0];
            float4 wb = w4[1];
            float4 wc = w4[2];
            float4 wd = w4[3];
            acc[0][0] += wa.x * xv0.x + wa.y * xv0.y;
            acc[0][1] += wa.x * xv1.x + wa.y * xv1.y;
            acc[1][0] += wa.z * xv0.x + wa.w * xv0.y;
            acc[1][1] += wa.z * xv1.x + wa.w * xv1.y;
            acc[2][0] += wb.x * xv0.x + wb.y * xv0.y;
            acc[2][1] += wb.x * xv1.x + wb.y * xv1.y;
            acc[3][0] += wb.z * xv0.x + wb.w * xv0.y;
            acc[3][1] += wb.z * xv1.x + wb.w * xv1.y;
            acc[4][0] += wc.x * xv0.x + wc.y * xv0.y;
            acc[4][1] += wc.x * xv1.x + wc.y * xv1.y;
            acc[5][0] += wc.z * xv0.x + wc.w * xv0.y;
            acc[5][1] += wc.z * xv1.x + wc.w * xv1.y;
            acc[6][0] += wd.x * xv0.x + wd.y * xv0.y;
            acc[6][1] += wd.x * xv1.x + wd.y * xv1.y;
            acc[7][0] += wd.z * xv0.x + wd.w * xv0.y;
            acc[7][1] += wd.z * xv1.x + wd.w * xv1.y;
        }

        if (hasNext) {
            __syncthreads();
            float4* dst = reinterpret_cast<float4*>(w_s[cur ^ 1]);
            if (tid       < W1_SLICE4) dst[tid]       = pf0;
            if (tid + 128 < W1_SLICE4) dst[tid + 128] = pf1;
            if (tid + 256 < W1_SLICE4) dst[tid + 256] = pf2;
            if (tid + 384 < W1_SLICE4) dst[tid + 384] = pf3;
            __syncthreads();
        }
    }

    const int t0g = tbase + lane;
    const int t1g = t0g + 32;
    const bool ok1 = (t1g < L1);
    #pragma unroll
    for (int u = 0; u < 8; u++) {
        int oc = oc0 + u;
        float bsv = __ldg(bias + oc);
        float v0 = acc[u][0] + bsv;
        float v1 = acc[u][1] + bsv;
        g_y1[((size_t)b * C1 + oc) * L1 + t0g] = v0;
        if (ok1) g_y1[((size_t)b * C1 + oc) * L1 + t1g] = v1;
        float s  = v0 + (ok1 ? v1 : 0.f);
        float s2 = v0 * v0 + (ok1 ? v1 * v1 : 0.f);
        s  = warp_sum(s);
        s2 = warp_sum(s2);
        if (lane == 0) {
            atomicAdd(&g_stats1[oc], s);
            atomicAdd(&g_stats1[32 + oc], s2);
        }
    }
}

// ---------------- kernel 3: conv2 (BN1 finalize+relu fused) + BN2 stats
// grid 512; block 256 = 8 warps; warp -> 4 oc; lane -> t2 = {lane, lane+32,
// lane+64}. Weights staged per-ci into double-buffered smem (3.2 KB slice):
// per tap = 3 scalar LDS (x) + 1 uniform LDS.128 (w) + 12 FFMA.
#define SMEM2_FLOATS (C2 * L1)            // 15872
#define SMEM2_BYTES  (SMEM2_FLOATS * 4)   // 63488
#define W2_SLICE4 200                     // float4 per ci slice (25*32 floats)

__global__ __launch_bounds__(256) void conv2_kernel(
    const float* __restrict__ bias,
    const float* __restrict__ bn1g, const float* __restrict__ bn1b)
{
    extern __shared__ float a_s[];        // [32][496]
    __shared__ __align__(16) float w_s[2][25 * C2];   // 2 x 3200 B
    __shared__ float bn1_s[64];

    const int b = blockIdx.x;
    const int tid = threadIdx.x;

    if (tid < 32) {
        const float invN = 1.f / (float)(BATCH * L1);
        float m = g_stats1[tid] * invN;
        float v = g_stats1[32 + tid] * invN - m * m;
        float sc = bn1g[tid] * rsqrtf(v + EPS);
        bn1_s[tid] = sc;
        bn1_s[32 + tid] = bn1b[tid] - m * sc;
    }
    const float4* wsrc = reinterpret_cast<const float4*>(g_w2s);
    if (tid < W2_SLICE4)
        reinterpret_cast<float4*>(w_s[0])[tid] = __ldg(wsrc + tid);
    __syncthreads();

    const float4* y1v = reinterpret_cast<const float4*>(g_y1 + (size_t)b * C2 * L1);
    float4* av = reinterpret_cast<float4*>(a_s);
    for (int i = tid; i < C2 * 124; i += 256) {
        int ci = i / 124;
        float sc = bn1_s[ci], sh = bn1_s[32 + ci];
        float4 v = __ldg(y1v + i);
        v.x = fmaxf(v.x * sc + sh, 0.f);
        v.y = fmaxf(v.y * sc + sh, 0.f);
        v.z = fmaxf(v.z * sc + sh, 0.f);
        v.w = fmaxf(v.w * sc + sh, 0.f);
        av[i] = v;
    }
    __syncthreads();

    const int lane = tid & 31;
    const int oc0  = (tid >> 5) * 4;
    const int p0 = lane * S2;
    const int p1 = p0 + 160;
    const bool ok2 = (lane + 64 < L2);
    const int p2 = ok2 ? p0 + 320 : 0;

    float acc[4][3];
    #pragma unroll
    for (int u = 0; u < 4; u++) { acc[u][0] = 0.f; acc[u][1] = 0.f; acc[u][2] = 0.f; }

    for (int ci = 0; ci < C2; ci++) {
        const int cur = ci & 1;
        const bool hasNext = (ci + 1 < C2);
        float4 pf;
        if (hasNext && tid < W2_SLICE4)
            pf = __ldg(wsrc + (ci + 1) * W2_SLICE4 + tid);

        const float* xr = a_s + ci * L1;
        const float* wr = w_s[cur] + oc0;
        #pragma unroll 5
        for (int t = 0; t < 25; t++) {
            float xA = xr[p0 + t];
            float xB = xr[p1 + t];
            float xC = xr[p2 + t];
            float4 wv = *reinterpret_cast<const float4*>(wr + t * C2);
            acc[0][0] += wv.x * xA; acc[0][1] += wv.x * xB; acc[0][2] += wv.x * xC;
            acc[1][0] += wv.y * xA; acc[1][1] += wv.y * xB; acc[1][2] += wv.y * xC;
            acc[2][0] += wv.z * xA; acc[2][1] += wv.z * xB; acc[2][2] += wv.z * xC;
            acc[3][0] += wv.w * xA; acc[3][1] += wv.w * xB; acc[3][2] += wv.w * xC;
        }

        if (hasNext) {
            __syncthreads();
            if (tid < W2_SLICE4)
                reinterpret_cast<float4*>(w_s[cur ^ 1])[tid] = pf;
            __syncthreads();
        }
    }

    #pragma unroll
    for (int u = 0; u < 4; u++) {
        int oc = oc0 + u;
        float bsv = __ldg(bias + oc);
        float v0 = acc[u][0] + bsv;
        float v1 = acc[u][1] + bsv;
        float v2 = acc[u][2] + bsv;
        float* yo = g_y2 + ((size_t)b * C2 + oc) * L2;
        yo[lane] = v0;
        yo[lane + 32] = v1;
        if (ok2) yo[lane + 64] = v2;
        float s  = v0 + v1 + (ok2 ? v2 : 0.f);
        float s2 = v0 * v0 + v1 * v1 + (ok2 ? v2 * v2 : 0.f);
        s  = warp_sum(s);
        s2 = warp_sum(s2);
        if (lane == 0) {
            atomicAdd(&g_stats2[oc], s);
            atomicAdd(&g_stats2[32 + oc], s2);
        }
    }
}

// ---------------- kernel 4: BN2 finalize+relu, input projection, LN1 --
__global__ __launch_bounds__(256) void proj_kernel(
    const float* __restrict__ Wi, const float* __restrict__ bi,
    const float* __restrict__ ln1g, const float* __restrict__ ln1b,
    const float* __restrict__ bn2g, const float* __restrict__ bn2b)
{
    __shared__ float a_s[C2 * L2];
    __shared__ float Wi_s[32 * 33];
    __shared__ float bn2_s[64];

    const int b = blockIdx.x;
    const int tid = threadIdx.x;

    if (tid < 32) {
        const float invN = 1.f / (float)(BATCH * L2);
        float m = g_stats2[tid] * invN;
        float v = g_stats2[32 + tid] * invN - m * m;
        float sc = bn2g[tid] * rsqrtf(v + EPS);
        bn2_s[tid] = sc;
        bn2_s[32 + tid] = bn2b[tid] - m * sc;
    }
    __syncthreads();

    for (int i = tid; i < C2 * L2; i += 256) {
        int c = i / L2;
        float v = g_y2[(size_t)b * C2 * L2 + i];
        a_s[i] = fmaxf(v * bn2_s[c] + bn2_s[32 + c], 0.f);
    }
    for (int i = tid; i < 32 * 32; i += 256)
        Wi_s[(i >> 5) * 33 + (i & 31)] = Wi[i];
    __syncthreads();

    const int lane = tid & 31;
    const int wp = tid >> 5;
    const float biv = bi[lane];
    const float gv = ln1g[lane], bv = ln1b[lane];

    for (int t = wp; t < L2; t += 8) {
        float z = biv;
        #pragma unroll
        for (int c = 0; c < 32; c++)
            z += Wi_s[lane * 33 + c] * a_s[c * L2 + t];
        float m = warp_sum(z) * (1.f / 32.f);
        float d = z - m;
        float var = warp_sum(d * d) * (1.f / 32.f);
        float r = rsqrtf(var + EPS);
        g_xt[((size_t)t * BATCH + b) * LAT + lane] = d * r * gv + bv;
    }
}

// ---------------- kernel 5: recurrent scan + pool + output proj -------
__global__ __launch_bounds__(128) void rnn_kernel(
    const float* __restrict__ Wh, const float* __restrict__ bh,
    const float* __restrict__ ln2g, const float* __restrict__ ln2b,
    const float* __restrict__ Wr, const float* __restrict__ br,
    const float* __restrict__ Wo, const float* __restrict__ bo,
    float* __restrict__ out)
{
    __shared__ float Wh_s[64 * 33];
    __shared__ float Wr_s[32 * 65];
    __shared__ float Wo_s[32 * 33];

    const int tid = threadIdx.x;
    const int lane = tid & 31;
    const int wp = tid >> 5;
    for (int i = tid; i < 64 * 32; i += 128) Wh_s[(i >> 5) * 33 + (i & 31)] = Wh[i];
    for (int i = tid; i < 32 * 64; i += 128) Wr_s[(i / 64) * 65 + (i % 64)] = Wr[i];
    for (int i = tid; i < 32 * 32; i += 128) Wo_s[(i >> 5) * 33 + (i & 31)] = Wo[i];
    __syncthreads();

    const int b = blockIdx.x * 4 + wp;
    const float bh0 = bh[lane], bh1 = bh[lane + 32];
    const float gA = ln2g[lane], bA = ln2b[lane];
    const float gB = ln2g[lane + 32], bB = ln2b[lane + 32];
    const float brl = br[lane];

    float h = 0.f, psum = 0.f;
    for (int t = 0; t < TSTEPS; t++) {
        float c = g_xt[((size_t)t * BATCH + b) * LAT + lane] + h;
        float a0a = bh0, a0b = 0.f, a1a = bh1, a1b = 0.f;
        #pragma unroll
        for (int j = 0; j < 32; j += 2) {
            float cj0 = __shfl_sync(0xffffffffu, c, j);
            float cj1 = __shfl_sync(0xffffffffu, c, j + 1);
            a0a += Wh_s[lane * 33 + j] * cj0;
            a0b += Wh_s[lane * 33 + j + 1] * cj1;
            a1a += Wh_s[(lane + 32) * 33 + j] * cj0;
            a1b += Wh_s[(lane + 32) * 33 + j + 1] * cj1;
        }
        float a0 = fmaxf(a0a + a0b, 0.f);
        float a1 = fmaxf(a1a + a1b, 0.f);
        float m = warp_sum(a0 + a1) * (1.f / 64.f);
        float d0 = a0 - m, d1 = a1 - m;
        float var = warp_sum(d0 * d0 + d1 * d1) * (1.f / 64.f);
        float r = rsqrtf(var + EPS);
        float n0 = d0 * r * gA + bA;
        float n1 = d1 * r * gB + bB;
        float acca = brl, accb = 0.f;
        #pragma unroll
        for (int i = 0; i < 32; i++) {
            float v0 = __shfl_sync(0xffffffffu, n0, i);
            float v1 = __shfl_sync(0xffffffffu, n1, i);
            acca += Wr_s[lane * 65 + i] * v0;
            accb += Wr_s[lane * 65 + 32 + i] * v1;
        }
        h = tanhf(acca + accb);
        psum += h;
    }
    float p = psum * (1.f / (float)TSTEPS);
    float o = bo[lane];
    #pragma unroll
    for (int j = 0; j < 32; j++)
        o += Wo_s[lane * 33 + j] * __shfl_sync(0xffffffffu, p, j);
    out[b * 32 + lane] = o;
}

// ---------------- launch ----------------
extern "C" void kernel_launch(void* const* d_in, const int* in_sizes, int n_in,
                              void* d_out, int out_size)
{
    const float* x    = (const float*)d_in[0];
    const float* c1w  = (const float*)d_in[1];
    const float* c1b  = (const float*)d_in[2];
    const float* bn1g = (const float*)d_in[3];
    const float* bn1b = (const float*)d_in[4];
    const float* c2w  = (const float*)d_in[5];
    const float* c2b  = (const float*)d_in[6];
    const float* bn2g = (const float*)d_in[7];
    const float* bn2b = (const float*)d_in[8];
    const float* Wi   = (const float*)d_in[9];
    const float* bi   = (const float*)d_in[10];
    const float* ln1g = (const float*)d_in[11];
    const float* ln1b = (const float*)d_in[12];
    const float* Wh   = (const float*)d_in[13];
    const float* bh   = (const float*)d_in[14];
    const float* ln2g = (const float*)d_in[15];
    const float* ln2b = (const float*)d_in[16];
    const float* Wr   = (const float*)d_in[17];
    const float* br   = (const float*)d_in[18];
    const float* Wo   = (const float*)d_in[19];
    const float* bo   = (const float*)d_in[20];
    float* out = (float*)d_out;

    static bool attr_done = false;
    if (!attr_done) {
        cudaFuncSetAttribute(conv2_kernel, cudaFuncAttributeMaxDynamicSharedMemorySize, SMEM2_BYTES);
        attr_done = true;
    }

    prep_kernel<<<64, 256>>>(c1w, c2w);
    conv1_kernel<<<dim3(8, BATCH), 128>>>(x, c1b);
    conv2_kernel<<<BATCH, 256, SMEM2_BYTES>>>(c2b, bn1g, bn1b);
    proj_kernel<<<BATCH, 256>>>(Wi, bi, ln1g, ln1b, bn2g, bn2b);
    rnn_kernel<<<BATCH / 4, 128>>>(Wh, bh, ln2g, ln2b, Wr, br, Wo, bo, out);
}

// round 15
// speedup vs baseline: 1.8139x; 1.2256x over previous
#include <cuda_runtime.h>
#include <cstdint>

#define BATCH 512
#define CIN   12
#define LIN   5000
#define C1    32
#define K1    50
#define S1    10
#define L1    496
#define C2    32
#define K2    25
#define S2    5
#define L2    95
#define LAT   32
#define HID   64
#define TSTEPS L2
#define EPS   1e-5f

#define NCHUNK 75          // K = 600 = 5(a) * 120(cb), 8 per chunk
#define ZW    72           // z row stride (conflict-free: 72 mod 32 = 8)

// ---------------- device scratch (no allocation allowed) ----------------
// conv1 B fragments: [chunk(75)][ntile(4)][lane(32)] = {bhi0,bhi1,blo0,blo1}
__device__ __align__(16) uint4 g_B[NCHUNK * 4 * 32];
// conv2 weights: [ci][tap(25)][oc(32)] float
__device__ __align__(16) float g_w2s[C2 * 25 * C2];
__device__ float g_y1[BATCH * C1 * L1];
__device__ float g_y2[BATCH * C2 * L2];
__device__ float g_xt[TSTEPS * BATCH * LAT];
__device__ float g_stats1[64];
__device__ float g_stats2[64];

__device__ __forceinline__ float warp_sum(float v) {
    #pragma unroll
    for (int o = 16; o; o >>= 1) v += __shfl_xor_sync(0xffffffffu, v, o);
    return v;
}
__device__ __forceinline__ uint32_t f2tf32(float f) {
    uint32_t r;
    asm("cvt.rna.tf32.f32 %0, %1;" : "=r"(r) : "f"(f));
    return r;
}
__device__ __forceinline__ void tf32split(float x, uint32_t& hi, uint32_t& lo) {
    hi = f2tf32(x);
    lo = f2tf32(x - __uint_as_float(hi));
}
__device__ __forceinline__ void mma_tf32(float* d,
    uint32_t a0, uint32_t a1, uint32_t a2, uint32_t a3,
    uint32_t b0, uint32_t b1)
{
    asm volatile(
        "mma.sync.aligned.m16n8k8.row.col.f32.tf32.tf32.f32 "
        "{%0,%1,%2,%3},{%4,%5,%6,%7},{%8,%9},{%0,%1,%2,%3};"
        : "+f"(d[0]), "+f"(d[1]), "+f"(d[2]), "+f"(d[3])
        : "r"(a0), "r"(a1), "r"(a2), "r"(a3), "r"(b0), "r"(b1));
}

// ---------------- kernel 0: zero stats + build weight layouts ----------
__global__ __launch_bounds__(256) void prep_kernel(
    const float* __restrict__ c1w, const float* __restrict__ c2w)
{
    int gid = blockIdx.x * 256 + threadIdx.x;
    int stride = gridDim.x * 256;
    if (gid < 64) { g_stats1[gid] = 0.f; g_stats2[gid] = 0.f; }
    // conv1 B fragments. k = a*120 + cb; cb = ci*10 + bphase; tap j = 10a + bphase.
    // b0 = B[k0+tig][oc], b1 = B[k0+tig+4][oc], oc = nt*8 + (lane>>2).
    for (int i = gid; i < NCHUNK * 4 * 32; i += stride) {
        int lane = i & 31;
        int nt   = (i >> 5) & 3;
        int c    = i >> 7;
        int tig  = lane & 3;
        int g    = lane >> 2;
        int oc   = nt * 8 + g;
        int a    = c / 15;
        int cc   = c % 15;
        int cb0  = cc * 8 + tig;
        int cb1  = cb0 + 4;
        int ci0 = cb0 / 10, bp0 = cb0 % 10;
        int ci1 = cb1 / 10, bp1 = cb1 % 10;
        float w0 = c1w[(oc * CIN + ci0) * K1 + 10 * a + bp0];
        float w1 = c1w[(oc * CIN + ci1) * K1 + 10 * a + bp1];
        uint32_t h0, l0, h1, l1;
        tf32split(w0, h0, l0);
        tf32split(w1, h1, l1);
        g_B[i] = make_uint4(h0, h1, l0, l1);
    }
    // conv2: idx = (ci*25 + t)*32 + oc
    for (int i = gid; i < C2 * 25 * C2; i += stride) {
        int oc = i & 31;
        int rest = i >> 5;
        int t = rest % 25;
        int ci = rest / 25;
        g_w2s[i] = c2w[(oc * C2 + ci) * K2 + t];
    }
}

// ---------------- kernel 1: conv1 via 3xTF32 mma + BN1 stats ----------
// grid (8, 512): 64-position tiles. block 128 = 4 warps; warp wm owns rows
// [wm*16, wm*16+16) x all 32 oc. Implicit GEMM over K=600 (75 chunks of 8).
// A from smem z (phase-decomposed x, conflict-free), B from g_B (prefetched).
__global__ __launch_bounds__(128) void conv1_kernel(
    const float* __restrict__ x, const float* __restrict__ bias)
{
    __shared__ float z_s[120 * ZW];     // 34560 B

    const int b     = blockIdx.y;
    const int tbase = blockIdx.x * 64;
    const int tid   = threadIdx.x;
    const int xstart = tbase * S1;

    // stage z[cb][p] = x[ci][xstart + 10p + bphase], p in [0,68)
    for (int e = tid; e < 120 * 68; e += 128) {
        int cb = e / 68, p = e % 68;
        int ci = cb / 10, bp = cb % 10;
        int gp = xstart + 10 * p + bp;
        z_s[cb * ZW + p] = (gp < LIN)
            ? __ldg(x + (size_t)(b * CIN + ci) * LIN + gp) : 0.f;
    }
    __syncthreads();

    const int lane = tid & 31;
    const int wm   = tid >> 5;
    const int tig  = lane & 3;
    const int g    = lane >> 2;

    float acc[4][4];
    #pragma unroll
    for (int nt = 0; nt < 4; nt++)
        #pragma unroll
        for (int k = 0; k < 4; k++) acc[nt][k] = 0.f;

    const uint4* gBl = g_B + lane;
    uint4 cur[4], pf[4];
    #pragma unroll
    for (int nt = 0; nt < 4; nt++) cur[nt] = __ldg(gBl + nt * 32);

    int c = 0;
    for (int a = 0; a < 5; a++) {
        int zoff = tig * ZW + wm * 16 + g + a;
        #pragma unroll 3
        for (int cc = 0; cc < 15; cc++) {
            // prefetch next chunk's B fragments
            if (c < NCHUNK - 1) {
                const uint4* np = gBl + (size_t)(c + 1) * 128;
                #pragma unroll
                for (int nt = 0; nt < 4; nt++) pf[nt] = __ldg(np + nt * 32);
            }
            // A fragments (conflict-free LDS), 3xTF32 split
            float x0 = z_s[zoff];            // A[g][tig]
            float x1 = z_s[zoff + 8];        // A[g+8][tig]
            float x2 = z_s[zoff + 4 * ZW];   // A[g][tig+4]
            float x3 = z_s[zoff + 4 * ZW + 8];
            uint32_t ah0, al0, ah1, al1, ah2, al2, ah3, al3;
            tf32split(x0, ah0, al0);
            tf32split(x1, ah1, al1);
            tf32split(x2, ah2, al2);
            tf32split(x3, ah3, al3);
            #pragma unroll
            for (int nt = 0; nt < 4; nt++) {
                uint4 B = cur[nt];
                mma_tf32(acc[nt], ah0, ah1, ah2, ah3, B.x, B.y);  // hi*hi
                mma_tf32(acc[nt], ah0, ah1, ah2, ah3, B.z, B.w);  // hi*lo
                mma_tf32(acc[nt], al0, al1, al2, al3, B.x, B.y);  // lo*hi
            }
            #pragma unroll
            for (int nt = 0; nt < 4; nt++) cur[nt] = pf[nt];
            zoff += 8 * ZW;
            c++;
        }
    }

    // epilogue: bias, store, BN1 stats
    const int t0 = tbase + wm * 16 + g;
    const int t1 = t0 + 8;
    const bool ok0 = (t0 < L1);
    const bool ok1 = (t1 < L1);
    #pragma unroll
    for (int nt = 0; nt < 4; nt++) {
        int oce = nt * 8 + 2 * tig;
        int oco = oce + 1;
        float be = __ldg(bias + oce);
        float bo = __ldg(bias + oco);
        float v00 = acc[nt][0] + be;   // D[g][2tig]
        float v01 = acc[nt][1] + bo;   // D[g][2tig+1]
        float v10 = acc[nt][2] + be;   // D[g+8][2tig]
        float v11 = acc[nt][3] + bo;   // D[g+8][2tig+1]
        float* ye = g_y1 + ((size_t)b * C1 + oce) * L1;
        float* yo = g_y1 + ((size_t)b * C1 + oco) * L1;
        if (ok0) { ye[t0] = v00; yo[t0] = v01; }
        if (ok1) { ye[t1] = v10; yo[t1] = v11; }
        float se = (ok0 ? v00 : 0.f) + (ok1 ? v10 : 0.f);
        float qe = (ok0 ? v00 * v00 : 0.f) + (ok1 ? v10 * v10 : 0.f);
        float so = (ok0 ? v01 : 0.f) + (ok1 ? v11 : 0.f);
        float qo = (ok0 ? v01 * v01 : 0.f) + (ok1 ? v11 * v11 : 0.f);
        // reduce over g (lane bits 2..4)
        #pragma unroll
        for (int o = 4; o < 32; o <<= 1) {
            se += __shfl_xor_sync(0xffffffffu, se, o);
            qe += __shfl_xor_sync(0xffffffffu, qe, o);
            so += __shfl_xor_sync(0xffffffffu, so, o);
            qo += __shfl_xor_sync(0xffffffffu, qo, o);
        }
        if (g == 0) {
            atomicAdd(&g_stats1[oce], se);
            atomicAdd(&g_stats1[32 + oce], qe);
            atomicAdd(&g_stats1[oco], so);
            atomicAdd(&g_stats1[32 + oco], qo);
        }
    }
}

// ---------------- kernel 3: conv2 (BN1 finalize+relu fused) + BN2 stats
// grid 512; block 256 = 8 warps; warp -> 4 oc; lane -> t2 = {lane, lane+32,
// lane+64}. Weights staged per-ci into double-buffered smem.
#define SMEM2_FLOATS (C2 * L1)            // 15872
#define SMEM2_BYTES  (SMEM2_FLOATS * 4)   // 63488
#define W2_SLICE4 200                     // float4 per ci slice (25*32 floats)

__global__ __launch_bounds__(256) void conv2_kernel(
    const float* __restrict__ bias,
    const float* __restrict__ bn1g, const float* __restrict__ bn1b)
{
    extern __shared__ float a_s[];        // [32][496]
    __shared__ __align__(16) float w_s[2][25 * C2];   // 2 x 3200 B
    __shared__ float bn1_s[64];

    const int b = blockIdx.x;
    const int tid = threadIdx.x;

    if (tid < 32) {
        const float invN = 1.f / (float)(BATCH * L1);
        float m = g_stats1[tid] * invN;
        float v = g_stats1[32 + tid] * invN - m * m;
        float sc = bn1g[tid] * rsqrtf(v + EPS);
        bn1_s[tid] = sc;
        bn1_s[32 + tid] = bn1b[tid] - m * sc;
    }
    const float4* wsrc = reinterpret_cast<const float4*>(g_w2s);
    if (tid < W2_SLICE4)
        reinterpret_cast<float4*>(w_s[0])[tid] = __ldg(wsrc + tid);
    __syncthreads();

    const float4* y1v = reinterpret_cast<const float4*>(g_y1 + (size_t)b * C2 * L1);
    float4* av = reinterpret_cast<float4*>(a_s);
    for (int i = tid; i < C2 * 124; i += 256) {
        int ci = i / 124;
        float sc = bn1_s[ci], sh = bn1_s[32 + ci];
        float4 v = __ldg(y1v + i);
        v.x = fmaxf(v.x * sc + sh, 0.f);
        v.y = fmaxf(v.y * sc + sh, 0.f);
        v.z = fmaxf(v.z * sc + sh, 0.f);
        v.w = fmaxf(v.w * sc + sh, 0.f);
        av[i] = v;
    }
    __syncthreads();

    const int lane = tid & 31;
    const int oc0  = (tid >> 5) * 4;
    const int p0 = lane * S2;
    const int p1 = p0 + 160;
    const bool ok2 = (lane + 64 < L2);
    const int p2 = ok2 ? p0 + 320 : 0;

    float acc[4][3];
    #pragma unroll
    for (int u = 0; u < 4; u++) { acc[u][0] = 0.f; acc[u][1] = 0.f; acc[u][2] = 0.f; }

    for (int ci = 0; ci < C2; ci++) {
        const int cur = ci & 1;
        const bool hasNext = (ci + 1 < C2);
        float4 pfv;
        if (hasNext && tid < W2_SLICE4)
            pfv = __ldg(wsrc + (ci + 1) * W2_SLICE4 + tid);

        const float* xr = a_s + ci * L1;
        const float* wr = w_s[cur] + oc0;
        #pragma unroll 5
        for (int t = 0; t < 25; t++) {
            float xA = xr[p0 + t];
            float xB = xr[p1 + t];
            float xC = xr[p2 + t];
            float4 wv = *reinterpret_cast<const float4*>(wr + t * C2);
            acc[0][0] += wv.x * xA; acc[0][1] += wv.x * xB; acc[0][2] += wv.x * xC;
            acc[1][0] += wv.y * xA; acc[1][1] += wv.y * xB; acc[1][2] += wv.y * xC;
            acc[2][0] += wv.z * xA; acc[2][1] += wv.z * xB; acc[2][2] += wv.z * xC;
            acc[3][0] += wv.w * xA; acc[3][1] += wv.w * xB; acc[3][2] += wv.w * xC;
        }

        if (hasNext) {
            __syncthreads();
            if (tid < W2_SLICE4)
                reinterpret_cast<float4*>(w_s[cur ^ 1])[tid] = pfv;
            __syncthreads();
        }
    }

    #pragma unroll
    for (int u = 0; u < 4; u++) {
        int oc = oc0 + u;
        float bsv = __ldg(bias + oc);
        float v0 = acc[u][0] + bsv;
        float v1 = acc[u][1] + bsv;
        float v2 = acc[u][2] + bsv;
        float* yo = g_y2 + ((size_t)b * C2 + oc) * L2;
        yo[lane] = v0;
        yo[lane + 32] = v1;
        if (ok2) yo[lane + 64] = v2;
        float s  = v0 + v1 + (ok2 ? v2 : 0.f);
        float s2 = v0 * v0 + v1 * v1 + (ok2 ? v2 * v2 : 0.f);
        s  = warp_sum(s);
        s2 = warp_sum(s2);
        if (lane == 0) {
            atomicAdd(&g_stats2[oc], s);
            atomicAdd(&g_stats2[32 + oc], s2);
        }
    }
}

// ---------------- kernel 4: BN2 finalize+relu, input projection, LN1 --
__global__ __launch_bounds__(256) void proj_kernel(
    const float* __restrict__ Wi, const float* __restrict__ bi,
    const float* __restrict__ ln1g, const float* __restrict__ ln1b,
    const float* __restrict__ bn2g, const float* __restrict__ bn2b)
{
    __shared__ float a_s[C2 * L2];
    __shared__ float Wi_s[32 * 33];
    __shared__ float bn2_s[64];

    const int b = blockIdx.x;
    const int tid = threadIdx.x;

    if (tid < 32) {
        const float invN = 1.f / (float)(BATCH * L2);
        float m = g_stats2[tid] * invN;
        float v = g_stats2[32 + tid] * invN - m * m;
        float sc = bn2g[tid] * rsqrtf(v + EPS);
        bn2_s[tid] = sc;
        bn2_s[32 + tid] = bn2b[tid] - m * sc;
    }
    __syncthreads();

    for (int i = tid; i < C2 * L2; i += 256) {
        int c = i / L2;
        float v = g_y2[(size_t)b * C2 * L2 + i];
        a_s[i] = fmaxf(v * bn2_s[c] + bn2_s[32 + c], 0.f);
    }
    for (int i = tid; i < 32 * 32; i += 256)
        Wi_s[(i >> 5) * 33 + (i & 31)] = Wi[i];
    __syncthreads();

    const int lane = tid & 31;
    const int wp = tid >> 5;
    const float biv = bi[lane];
    const float gv = ln1g[lane], bv = ln1b[lane];

    for (int t = wp; t < L2; t += 8) {
        float z = biv;
        #pragma unroll
        for (int c = 0; c < 32; c++)
            z += Wi_s[lane * 33 + c] * a_s[c * L2 + t];
        float m = warp_sum(z) * (1.f / 32.f);
        float d = z - m;
        float var = warp_sum(d * d) * (1.f / 32.f);
        float r = rsqrtf(var + EPS);
        g_xt[((size_t)t * BATCH + b) * LAT + lane] = d * r * gv + bv;
    }
}

// ---------------- kernel 5: recurrent scan + pool + output proj -------
__global__ __launch_bounds__(128) void rnn_kernel(
    const float* __restrict__ Wh, const float* __restrict__ bh,
    const float* __restrict__ ln2g, const float* __restrict__ ln2b,
    const float* __restrict__ Wr, const float* __restrict__ br,
    const float* __restrict__ Wo, const float* __restrict__ bo,
    float* __restrict__ out)
{
    __shared__ float Wh_s[64 * 33];
    __shared__ float Wr_s[32 * 65];
    __shared__ float Wo_s[32 * 33];

    const int tid = threadIdx.x;
    const int lane = tid & 31;
    const int wp = tid >> 5;
    for (int i = tid; i < 64 * 32; i += 128) Wh_s[(i >> 5) * 33 + (i & 31)] = Wh[i];
    for (int i = tid; i < 32 * 64; i += 128) Wr_s[(i / 64) * 65 + (i % 64)] = Wr[i];
    for (int i = tid; i < 32 * 32; i += 128) Wo_s[(i >> 5) * 33 + (i & 31)] = Wo[i];
    __syncthreads();

    const int b = blockIdx.x * 4 + wp;
    const float bh0 = bh[lane], bh1 = bh[lane + 32];
    const float gA = ln2g[lane], bA = ln2b[lane];
    const float gB = ln2g[lane + 32], bB = ln2b[lane + 32];
    const float brl = br[lane];

    float h = 0.f, psum = 0.f;
    for (int t = 0; t < TSTEPS; t++) {
        float c = g_xt[((size_t)t * BATCH + b) * LAT + lane] + h;
        float a0a = bh0, a0b = 0.f, a1a = bh1, a1b = 0.f;
        #pragma unroll
        for (int j = 0; j < 32; j += 2) {
            float cj0 = __shfl_sync(0xffffffffu, c, j);
            float cj1 = __shfl_sync(0xffffffffu, c, j + 1);
            a0a += Wh_s[lane * 33 + j] * cj0;
            a0b += Wh_s[lane * 33 + j + 1] * cj1;
            a1a += Wh_s[(lane + 32) * 33 + j] * cj0;
            a1b += Wh_s[(lane + 32) * 33 + j + 1] * cj1;
        }
        float a0 = fmaxf(a0a + a0b, 0.f);
        float a1 = fmaxf(a1a + a1b, 0.f);
        float m = warp_sum(a0 + a1) * (1.f / 64.f);
        float d0 = a0 - m, d1 = a1 - m;
        float var = warp_sum(d0 * d0 + d1 * d1) * (1.f / 64.f);
        float r = rsqrtf(var + EPS);
        float n0 = d0 * r * gA + bA;
        float n1 = d1 * r * gB + bB;
        float acca = brl, accb = 0.f;
        #pragma unroll
        for (int i = 0; i < 32; i++) {
            float v0 = __shfl_sync(0xffffffffu, n0, i);
            float v1 = __shfl_sync(0xffffffffu, n1, i);
            acca += Wr_s[lane * 65 + i] * v0;
            accb += Wr_s[lane * 65 + 32 + i] * v1;
        }
        h = tanhf(acca + accb);
        psum += h;
    }
    float p = psum * (1.f / (float)TSTEPS);
    float o = bo[lane];
    #pragma unroll
    for (int j = 0; j < 32; j++)
        o += Wo_s[lane * 33 + j] * __shfl_sync(0xffffffffu, p, j);
    out[b * 32 + lane] = o;
}

// ---------------- launch ----------------
extern "C" void kernel_launch(void* const* d_in, const int* in_sizes, int n_in,
                              void* d_out, int out_size)
{
    const float* x    = (const float*)d_in[0];
    const float* c1w  = (const float*)d_in[1];
    const float* c1b  = (const float*)d_in[2];
    const float* bn1g = (const float*)d_in[3];
    const float* bn1b = (const float*)d_in[4];
    const float* c2w  = (const float*)d_in[5];
    const float* c2b  = (const float*)d_in[6];
    const float* bn2g = (const float*)d_in[7];
    const float* bn2b = (const float*)d_in[8];
    const float* Wi   = (const float*)d_in[9];
    const float* bi   = (const float*)d_in[10];
    const float* ln1g = (const float*)d_in[11];
    const float* ln1b = (const float*)d_in[12];
    const float* Wh   = (const float*)d_in[13];
    const float* bh   = (const float*)d_in[14];
    const float* ln2g = (const float*)d_in[15];
    const float* ln2b = (const float*)d_in[16];
    const float* Wr   = (const float*)d_in[17];
    const float* br   = (const float*)d_in[18];
    const float* Wo   = (const float*)d_in[19];
    const float* bo   = (const float*)d_in[20];
    float* out = (float*)d_out;

    static bool attr_done = false;
    if (!attr_done) {
        cudaFuncSetAttribute(conv2_kernel, cudaFuncAttributeMaxDynamicSharedMemorySize, SMEM2_BYTES);
        attr_done = true;
    }

    prep_kernel<<<64, 256>>>(c1w, c2w);
    conv1_kernel<<<dim3(8, BATCH), 128>>>(x, c1b);
    conv2_kernel<<<BATCH, 256, SMEM2_BYTES>>>(c2b, bn1g, bn1b);
    proj_kernel<<<BATCH, 256>>>(Wi, bi, ln1g, ln1b, bn2g, bn2b);
    rnn_kernel<<<BATCH / 4, 128>>>(Wh, bh, ln2g, ln2b, Wr, br, Wo, bo, out);
}